// round 6
// baseline (speedup 1.0000x reference)
#include <cuda_runtime.h>
#include <stdint.h>

// Problem constants (fixed by setup_inputs)
#define B_  4
#define T_  24
#define C_  10
#define H_  128
#define W_  128
#define TC_ 365
#define DC_ 11
#define HID_ 64
#define DM_ 64
#define COUT_ (C_ + DM_)        // 74
#define PAD_VALUE (-1000.0f)

#define PLANE4_ (H_ * W_ / 4)   // 4096 float4 per plane
#define THREADS_ 512
#define ITERS_ (PLANE4_ / THREADS_)  // 8
#define FULLMASK_ 0xFFFFFFFFu

// --- dtype-agnostic date read -------------------------------------------
// Dates are in [0, 365). If the buffer is int64, every odd 32-bit word of
// the first n/2 logical elements is zero (real sorted int32 date data makes
// that astronomically unlikely). Reading only n/2 logical elements stays
// in-bounds under BOTH interpretations. Warp-parallel check + ballot.
__device__ __forceinline__ bool detect_i64_warp(const int* p, int npairs) {
    const int lane = threadIdx.x & 31;
    int bad = 0;
    if (lane < npairs)       bad |= p[2 * lane + 1];
    if (lane + 32 < npairs)  bad |= p[2 * (lane + 32) + 1];
    unsigned m = __ballot_sync(FULLMASK_, bad != 0);
    return m == 0u;   // all odd words zero -> int64
}

__device__ __forceinline__ long long read_date(const void* p, int i, bool i64) {
    return i64 ? ((const long long*)p)[i] : (long long)((const int*)p)[i];
}

// --- Fused kernel: assemble output [B,T,74,H,W] -------------------------
// One block per (bt, c) plane, 512 threads, 8 float4/thread.
//  c < 10 : batched streaming plane copy (proven R2 shape).
//  c >= 10: WARP-AUTONOMOUS scalar compute (no smem, no barriers) followed
//           by 8 streaming STG.128 per thread. Each warp resolves its own
//           dependent-load chain and starts storing immediately.
__global__ __launch_bounds__(THREADS_)
void assemble_fused_kernel(const float4* __restrict__ sat,
                           const void*  __restrict__ dates_sat,
                           const void*  __restrict__ dates_clim,
                           const float* __restrict__ input_clim,
                           const float* __restrict__ W1,
                           const float* __restrict__ b1,
                           const float* __restrict__ W2,
                           const float* __restrict__ b2,
                           float4* __restrict__ out) {
    const int c   = blockIdx.x;   // 0..73 (uniform per block -> no divergence)
    const int bt  = blockIdx.y;   // 0..95
    const int tid = threadIdx.x;  // 0..511

    float4* __restrict__ dst =
        out + ((size_t)bt * COUT_ + c) * (size_t)PLANE4_ + tid;

    if (c < C_) {
        // ---- plane copy path ----
        const float4* __restrict__ src =
            sat + ((size_t)bt * C_ + c) * (size_t)PLANE4_ + tid;
        float4 v[ITERS_];
#pragma unroll
        for (int i = 0; i < ITERS_; ++i)
            v[i] = __ldcs(src + i * THREADS_);
#pragma unroll
        for (int i = 0; i < ITERS_; ++i)
            __stcs(dst + i * THREADS_, v[i]);
    } else {
        // ---- broadcast path: warp-autonomous scalar compute ----
        const int m    = c - C_;          // feature index 0..63
        const int b    = bt / T_;
        const int lane = tid & 31;

        const bool i64s = detect_i64_warp((const int*)dates_sat,  (B_ * T_) / 2);
        const bool i64c = detect_i64_warp((const int*)dates_clim, 64);

        const long long target = read_date(dates_sat, bt, i64s);

        // first-match scan: 12 dates per lane, warp min-reduce of match idx
        int my_min = 0x7fffffff;
#pragma unroll
        for (int r = 0; r < 12; ++r) {
            const int j = lane + 32 * r;
            if (j < TC_ &&
                read_date(dates_clim, b * TC_ + j, i64c) == target &&
                j < my_min)
                my_min = j;
        }
#pragma unroll
        for (int off = 16; off > 0; off >>= 1)
            my_min = min(my_min, __shfl_xor_sync(FULLMASK_, my_min, off));

        const bool has = (my_min != 0x7fffffff);
        const int  idx = has ? my_min : 0;

        // lanes 0..10 gather clim; broadcast via shfl inside the FMA loop
        float my_clim = PAD_VALUE;
        if (lane < DC_ && has)
            my_clim = input_clim[(b * TC_ + idx) * DC_ + lane];

        // each lane computes hidden units k=lane and k=lane+32
        const int k0 = lane, k1 = lane + 32;
        float a0 = b1[k0], a1 = b1[k1];
#pragma unroll
        for (int d = 0; d < DC_; ++d) {
            const float cd = __shfl_sync(FULLMASK_, my_clim, d);
            a0 = fmaf(cd, W1[d * HID_ + k0], a0);
            a1 = fmaf(cd, W1[d * HID_ + k1], a1);
        }
        float partial = fmaxf(a0, 0.0f) * W2[k0 * DM_ + m]
                      + fmaxf(a1, 0.0f) * W2[k1 * DM_ + m];
#pragma unroll
        for (int off = 16; off > 0; off >>= 1)
            partial += __shfl_xor_sync(FULLMASK_, partial, off);

        const float s = partial + b2[m];
        const float4 v = make_float4(s, s, s, s);
#pragma unroll
        for (int i = 0; i < ITERS_; ++i)
            __stcs(dst + i * THREADS_, v);
    }
}

extern "C" void kernel_launch(void* const* d_in, const int* in_sizes, int n_in,
                              void* d_out, int out_size) {
    const float* input_sat  = (const float*)d_in[0];
    const void*  dates_sat  = d_in[1];
    const float* input_clim = (const float*)d_in[2];
    const void*  dates_clim = d_in[3];
    const float* W1 = (const float*)d_in[4];
    const float* b1 = (const float*)d_in[5];
    const float* W2 = (const float*)d_in[6];
    const float* b2 = (const float*)d_in[7];

    dim3 grid(COUT_, B_ * T_);
    assemble_fused_kernel<<<grid, THREADS_>>>(
        (const float4*)input_sat, dates_sat, dates_clim, input_clim,
        W1, b1, W2, b2, (float4*)d_out);
}

// round 7
// speedup vs baseline: 1.0666x; 1.0666x over previous
#include <cuda_runtime.h>
#include <stdint.h>

// Problem constants (fixed by setup_inputs)
#define B_  4
#define T_  24
#define C_  10
#define H_  128
#define W_  128
#define TC_ 365
#define DC_ 11
#define HID_ 64
#define DM_ 64
#define COUT_ (C_ + DM_)        // 74
#define PAD_VALUE (-1000.0f)

#define PLANE4_ (H_ * W_ / 4)   // 4096 float4 per plane
#define THREADS_ 512
#define ITERS_ (PLANE4_ / THREADS_)  // 8
#define FULLMASK_ 0xFFFFFFFFu

// --- dtype-agnostic date read -------------------------------------------
// Dates are in [0, 365). If the buffer is int64, every odd 32-bit word of
// the first n/2 logical elements is zero (real sorted int32 date data makes
// that astronomically unlikely). Reading only n/2 logical elements stays
// in-bounds under BOTH interpretations. Warp-parallel check + ballot.
__device__ __forceinline__ bool detect_i64_warp(const int* p, int npairs) {
    const int lane = threadIdx.x & 31;
    int bad = 0;
    if (lane < npairs)       bad |= p[2 * lane + 1];
    if (lane + 32 < npairs)  bad |= p[2 * (lane + 32) + 1];
    unsigned m = __ballot_sync(FULLMASK_, bad != 0);
    return m == 0u;   // all odd words zero -> int64
}

__device__ __forceinline__ long long read_date(const void* p, int i, bool i64) {
    return i64 ? ((const long long*)p)[i] : (long long)((const int*)p)[i];
}

// --- Fused kernel: assemble output [B,T,74,H,W] -------------------------
// One block per (bt, c) plane, 512 threads, 8 float4/thread.
//  c < 10 : batched streaming plane copy (proven R2 shape).
//  c >= 10: warp 0 alone computes the block's ONE clim_feat scalar
//           (single-warp date match + MLP, validated in R6), publishes it
//           through smem with ONE __syncthreads, then all 16 warps issue
//           8 streaming STG.128 each.
__global__ __launch_bounds__(THREADS_)
void assemble_fused_kernel(const float4* __restrict__ sat,
                           const void*  __restrict__ dates_sat,
                           const void*  __restrict__ dates_clim,
                           const float* __restrict__ input_clim,
                           const float* __restrict__ W1,
                           const float* __restrict__ b1,
                           const float* __restrict__ W2,
                           const float* __restrict__ b2,
                           float4* __restrict__ out) {
    const int c   = blockIdx.x;   // 0..73 (uniform per block -> no divergence)
    const int bt  = blockIdx.y;   // 0..95
    const int tid = threadIdx.x;  // 0..511

    float4* __restrict__ dst =
        out + ((size_t)bt * COUT_ + c) * (size_t)PLANE4_ + tid;

    if (c < C_) {
        // ---- plane copy path ----
        const float4* __restrict__ src =
            sat + ((size_t)bt * C_ + c) * (size_t)PLANE4_ + tid;
        float4 v[ITERS_];
#pragma unroll
        for (int i = 0; i < ITERS_; ++i)
            v[i] = __ldcs(src + i * THREADS_);
#pragma unroll
        for (int i = 0; i < ITERS_; ++i)
            __stcs(dst + i * THREADS_, v[i]);
    } else {
        // ---- broadcast path: warp 0 computes, everyone stores ----
        __shared__ float s_val;

        if (tid < 32) {
            const int m    = c - C_;      // feature index 0..63
            const int b    = bt / T_;
            const int lane = tid;

            const bool i64s = detect_i64_warp((const int*)dates_sat,
                                              (B_ * T_) / 2);
            const bool i64c = detect_i64_warp((const int*)dates_clim, 64);

            const long long target = read_date(dates_sat, bt, i64s);

            // first-match scan: 12 dates/lane, warp min-reduce of match idx
            int my_min = 0x7fffffff;
#pragma unroll
            for (int r = 0; r < 12; ++r) {
                const int j = lane + 32 * r;
                if (j < TC_ &&
                    read_date(dates_clim, b * TC_ + j, i64c) == target &&
                    j < my_min)
                    my_min = j;
            }
#pragma unroll
            for (int off = 16; off > 0; off >>= 1)
                my_min = min(my_min, __shfl_xor_sync(FULLMASK_, my_min, off));

            const bool has = (my_min != 0x7fffffff);
            const int  idx = has ? my_min : 0;

            // lanes 0..10 gather clim; broadcast via shfl in the FMA loop
            float my_clim = PAD_VALUE;
            if (lane < DC_ && has)
                my_clim = input_clim[(b * TC_ + idx) * DC_ + lane];

            // each lane computes hidden units k=lane and k=lane+32
            const int k0 = lane, k1 = lane + 32;
            float a0 = b1[k0], a1 = b1[k1];
#pragma unroll
            for (int d = 0; d < DC_; ++d) {
                const float cd = __shfl_sync(FULLMASK_, my_clim, d);
                a0 = fmaf(cd, W1[d * HID_ + k0], a0);
                a1 = fmaf(cd, W1[d * HID_ + k1], a1);
            }
            float partial = fmaxf(a0, 0.0f) * W2[k0 * DM_ + m]
                          + fmaxf(a1, 0.0f) * W2[k1 * DM_ + m];
#pragma unroll
            for (int off = 16; off > 0; off >>= 1)
                partial += __shfl_xor_sync(FULLMASK_, partial, off);

            if (lane == 0)
                s_val = partial + b2[m];
        }
        __syncthreads();

        const float s = s_val;
        const float4 v = make_float4(s, s, s, s);
#pragma unroll
        for (int i = 0; i < ITERS_; ++i)
            __stcs(dst + i * THREADS_, v);
    }
}

extern "C" void kernel_launch(void* const* d_in, const int* in_sizes, int n_in,
                              void* d_out, int out_size) {
    const float* input_sat  = (const float*)d_in[0];
    const void*  dates_sat  = d_in[1];
    const float* input_clim = (const float*)d_in[2];
    const void*  dates_clim = d_in[3];
    const float* W1 = (const float*)d_in[4];
    const float* b1 = (const float*)d_in[5];
    const float* W2 = (const float*)d_in[6];
    const float* b2 = (const float*)d_in[7];

    dim3 grid(COUT_, B_ * T_);
    assemble_fused_kernel<<<grid, THREADS_>>>(
        (const float4*)input_sat, dates_sat, dates_clim, input_clim,
        W1, b1, W2, b2, (float4*)d_out);
}